// round 14
// baseline (speedup 1.0000x reference)
#include <cuda_runtime.h>

#define C_DIM 512
#define K_DIM 19
#define K_PAD 20                       // padded class dim (pool partial layout)
#define KH    10                       // classes per pool-ksplit CTA
#define HW    16384
#define B_DIM 8
#define S_CHUNKS 16                    // pool chunks (1024 positions each)
#define NHALF (B_DIM * K_DIM * HW)     // elements per csplit partial half

typedef unsigned long long u64;

// ---- f32x2 packed helpers ----
__device__ __forceinline__ u64 pk2(float lo, float hi) {
    u64 r; asm("mov.b64 %0, {%1, %2};" : "=l"(r) : "f"(lo), "f"(hi)); return r;
}
__device__ __forceinline__ void upk2(u64 v, float& lo, float& hi) {
    asm("mov.b64 {%0, %1}, %2;" : "=f"(lo), "=f"(hi) : "l"(v));
}
__device__ __forceinline__ u64 ffma2(u64 a, u64 b, u64 c) {
    u64 d; asm("fma.rn.f32x2 %0, %1, %2, %3;" : "=l"(d) : "l"(a), "l"(b), "l"(c)); return d;
}

// Static scratch
__device__ float g_pre[2 * NHALF];                             // csplit partials (19.9MB)
__device__ float g_partial[B_DIM * S_CHUNKS * K_PAD * C_DIM];  // pooling partials (5.2MB)
__device__ float g_cf[B_DIM * K_DIM * C_DIM];                  // class features
__device__ float g_filters[B_DIM * K_DIM * C_DIM];             // dynamic filters

// ============================================================
// K1: pre-mask partial over half the channels -> g_pre.
// grid (32 pos-tiles, 2 csplit, 8 b), 256 thr (24 warps/SM at (256,3)),
// 2 pos/thread. Acc = 19 u64 = 38 regs. Inner step = 4 channels with
// 4-deep u64 prefetch -> 4 LDG.64 in flight/warp = 24KB/SM in flight.
// Dup'd-pair weights in smem; broadcast LDS.128 per 2 channels.
// ============================================================
__global__ void __launch_bounds__(256, 3) k_mask(
    const float* __restrict__ x, const float* __restrict__ Wm,
    const float* __restrict__ bm)
{
    __shared__ __align__(16) u64 wd[K_DIM * 256];   // dup pairs, 38912 B
    int tid = threadIdx.x;
    int split = blockIdx.y, b = blockIdx.z;
    int c0 = split * 256;

    for (int i = tid; i < K_DIM * 256; i += 256) {
        float w = Wm[(i >> 8) * C_DIM + c0 + (i & 255)];
        wd[i] = pk2(w, w);
    }
    __syncthreads();

    int p0 = blockIdx.x * 512 + tid * 2;
    const float* xb = x + ((size_t)b * C_DIM + c0) * HW + p0;

    u64 a[K_DIM];
    #pragma unroll
    for (int k = 0; k < K_DIM; k++) {
        float bv = (split == 0) ? __ldg(&bm[k]) : 0.0f;
        a[k] = pk2(bv, bv);
    }

    u64 x0 = *(const u64*)(xb + (size_t)0 * HW);
    u64 x1 = *(const u64*)(xb + (size_t)1 * HW);
    u64 x2 = *(const u64*)(xb + (size_t)2 * HW);
    u64 x3 = *(const u64*)(xb + (size_t)3 * HW);

    #pragma unroll 1
    for (int c = 0; c < 256; c += 4) {
        int cn = (c < 252) ? c + 4 : c;            // clamped prefetch
        u64 n0 = *(const u64*)(xb + (size_t)(cn + 0) * HW);
        u64 n1 = *(const u64*)(xb + (size_t)(cn + 1) * HW);
        u64 n2 = *(const u64*)(xb + (size_t)(cn + 2) * HW);
        u64 n3 = *(const u64*)(xb + (size_t)(cn + 3) * HW);
        #pragma unroll
        for (int k = 0; k < K_DIM; k++) {
            ulonglong2 wA = *(const ulonglong2*)&wd[k * 256 + c];      // ch c, c+1
            ulonglong2 wB = *(const ulonglong2*)&wd[k * 256 + c + 2];  // ch c+2, c+3
            a[k] = ffma2(wA.x, x0, a[k]);
            a[k] = ffma2(wA.y, x1, a[k]);
            a[k] = ffma2(wB.x, x2, a[k]);
            a[k] = ffma2(wB.y, x3, a[k]);
        }
        x0 = n0; x1 = n1; x2 = n2; x3 = n3;
    }

    float* gp = g_pre + (size_t)split * NHALF + ((size_t)b * K_DIM) * HW + p0;
    #pragma unroll
    for (int k = 0; k < K_DIM; k++)
        *(u64*)(gp + (size_t)k * HW) = a[k];
}

// ============================================================
// K2: pooling partials. grid (2 ksplit, 16 chunks, 8 b), 256 thr.
// Each CTA: 10 classes (padded), ALL 512 channels, chunk=1024 pos.
// mask = sigmoid(h0+h1) computed INLINE while staging into smem.
// Lane owns a channel-QUAD: one mask LDS.64 feeds 4 FFMA2.
// (R11-validated configuration.)
// ============================================================
__global__ void __launch_bounds__(256, 2) k_pool(const float* __restrict__ x)
{
    __shared__ u64 m2[KH * 512];   // 40960 B
    int tid = threadIdx.x;
    int ksplit = blockIdx.x, chunk = blockIdx.y, b = blockIdx.z;
    int p0 = chunk * 1024;
    int K0 = ksplit * KH;

    for (int i = tid; i < KH * 512; i += 256) {
        int kh = i >> 9, j = i & 511;
        int k = K0 + kh;
        if (k < K_DIM) {
            size_t off = ((size_t)b * K_DIM + k) * HW + p0 + 2 * j;
            u64 h0 = *(const u64*)(g_pre + off);
            u64 h1 = *(const u64*)(g_pre + NHALF + off);
            float a0, a1, b0, b1;
            upk2(h0, a0, a1); upk2(h1, b0, b1);
            float s0 = 1.0f / (1.0f + __expf(-(a0 + b0)));
            float s1 = 1.0f / (1.0f + __expf(-(a1 + b1)));
            m2[i] = pk2(s0, s1);
        } else {
            m2[i] = 0ull;
        }
    }
    __syncthreads();

    int warp = tid >> 5, lane = tid & 31;
    const float inv = 1.0f / (float)HW;
    const float* xbase = x + (size_t)b * C_DIM * HW + p0;

    for (int i = 0; i < 16; i++) {          // 8 warps x 16 = 128 quads = 512 ch
        int cbase = 4 * (warp + 8 * i);
        const float* xp0 = xbase + (size_t)(cbase + 0) * HW;
        const float* xp1 = xbase + (size_t)(cbase + 1) * HW;
        const float* xp2 = xbase + (size_t)(cbase + 2) * HW;
        const float* xp3 = xbase + (size_t)(cbase + 3) * HW;

        u64 a[4 * KH];
        #pragma unroll
        for (int j = 0; j < 4 * KH; j++) a[j] = 0ull;

        #pragma unroll 2
        for (int t = 0; t < 16; t++) {      // 16 pair-steps x 32 lanes = 512 pairs
            int idx = lane + 32 * t;
            u64 xv0 = *(const u64*)(xp0 + 2 * idx);
            u64 xv1 = *(const u64*)(xp1 + 2 * idx);
            u64 xv2 = *(const u64*)(xp2 + 2 * idx);
            u64 xv3 = *(const u64*)(xp3 + 2 * idx);
            #pragma unroll
            for (int kh = 0; kh < KH; kh++) {
                u64 m = m2[kh * 512 + idx];
                a[kh * 4 + 0] = ffma2(m, xv0, a[kh * 4 + 0]);
                a[kh * 4 + 1] = ffma2(m, xv1, a[kh * 4 + 1]);
                a[kh * 4 + 2] = ffma2(m, xv2, a[kh * 4 + 2]);
                a[kh * 4 + 3] = ffma2(m, xv3, a[kh * 4 + 3]);
            }
        }

        #pragma unroll
        for (int kh = 0; kh < KH; kh++) {
            float s[4];
            #pragma unroll
            for (int j = 0; j < 4; j++) {
                float lo, hi; upk2(a[kh * 4 + j], lo, hi); s[j] = lo + hi;
            }
            #pragma unroll
            for (int off = 16; off > 0; off >>= 1) {
                #pragma unroll
                for (int j = 0; j < 4; j++)
                    s[j] += __shfl_xor_sync(0xffffffffu, s[j], off);
            }
            if (lane == 0) {
                float* gp = &g_partial[(((size_t)b * S_CHUNKS + chunk) * K_PAD + K0 + kh) * C_DIM + cbase];
                gp[0] = s[0] * inv; gp[1] = s[1] * inv;
                gp[2] = s[2] * inv; gp[3] = s[3] * inv;
            }
        }
    }
}

// ============================================================
// K2b: reduce chunk partials -> class_feat. grid (19, 8), block 512.
// ============================================================
__global__ void __launch_bounds__(512) k_cf()
{
    int k = blockIdx.x, b = blockIdx.y;
    int c = threadIdx.x;
    const float* gp = g_partial + ((size_t)b * S_CHUNKS * K_PAD + k) * C_DIM + c;
    float sum = 0.0f;
    #pragma unroll 8
    for (int s = 0; s < S_CHUNKS; s++)
        sum += gp[(size_t)s * K_PAD * C_DIM];
    g_cf[((size_t)b * K_DIM + k) * C_DIM + c] = sum;
}

// ============================================================
// K2c: filters GEMV. grid (19, 8 osplit, 8 b) = 1216 CTAs, block 128.
// ============================================================
__global__ void __launch_bounds__(128) k_filters(
    const float* __restrict__ Wf, const float* __restrict__ bf)
{
    int k = blockIdx.x, osplit = blockIdx.y, b = blockIdx.z;
    int warp = threadIdx.x >> 5, lane = threadIdx.x & 31;

    const float4* cf4 = (const float4*)(g_cf + ((size_t)b * K_DIM + k) * C_DIM);
    float4 cfr[4];
    #pragma unroll
    for (int j = 0; j < 4; j++) cfr[j] = __ldg(&cf4[lane + 32 * j]);

    int obase = osplit * 64 + warp * 16;
    for (int g = 0; g < 4; g++) {
        int o = obase + 4 * g;
        const float4* w0 = (const float4*)(Wf + ((size_t)k * C_DIM + o + 0) * C_DIM);
        const float4* w1 = (const float4*)(Wf + ((size_t)k * C_DIM + o + 1) * C_DIM);
        const float4* w2 = (const float4*)(Wf + ((size_t)k * C_DIM + o + 2) * C_DIM);
        const float4* w3 = (const float4*)(Wf + ((size_t)k * C_DIM + o + 3) * C_DIM);

        float acc0 = 0.f, acc1 = 0.f, acc2 = 0.f, acc3 = 0.f;
        #pragma unroll
        for (int j = 0; j < 4; j++) {
            int idx = lane + 32 * j;
            float4 a = w0[idx], bb = w1[idx], cc = w2[idx], dd = w3[idx];
            float4 f = cfr[j];
            acc0 += a.x * f.x + a.y * f.y + a.z * f.z + a.w * f.w;
            acc1 += bb.x * f.x + bb.y * f.y + bb.z * f.z + bb.w * f.w;
            acc2 += cc.x * f.x + cc.y * f.y + cc.z * f.z + cc.w * f.w;
            acc3 += dd.x * f.x + dd.y * f.y + dd.z * f.z + dd.w * f.w;
        }
        #pragma unroll
        for (int off = 16; off > 0; off >>= 1) {
            acc0 += __shfl_xor_sync(0xffffffffu, acc0, off);
            acc1 += __shfl_xor_sync(0xffffffffu, acc1, off);
            acc2 += __shfl_xor_sync(0xffffffffu, acc2, off);
            acc3 += __shfl_xor_sync(0xffffffffu, acc3, off);
        }
        if (lane < 4) {
            float v = (lane == 0) ? acc0 : (lane == 1) ? acc1 : (lane == 2) ? acc2 : acc3;
            g_filters[((size_t)b * K_DIM + k) * C_DIM + o + lane] =
                v + bf[k * C_DIM + o + lane];
        }
    }
}

// ============================================================
// K3: pred partial over half the channels (same shape as k_mask).
// ============================================================
__global__ void __launch_bounds__(256, 3) k_pred(const float* __restrict__ x)
{
    __shared__ __align__(16) u64 wd[K_DIM * 256];
    int tid = threadIdx.x;
    int split = blockIdx.y, b = blockIdx.z;
    int c0 = split * 256;

    const float* fb = g_filters + (size_t)b * K_DIM * C_DIM;
    for (int i = tid; i < K_DIM * 256; i += 256) {
        float w = fb[(i >> 8) * C_DIM + c0 + (i & 255)];
        wd[i] = pk2(w, w);
    }
    __syncthreads();

    int p0 = blockIdx.x * 512 + tid * 2;
    const float* xb = x + ((size_t)b * C_DIM + c0) * HW + p0;

    u64 a[K_DIM];
    #pragma unroll
    for (int k = 0; k < K_DIM; k++) a[k] = 0ull;

    u64 x0 = *(const u64*)(xb + (size_t)0 * HW);
    u64 x1 = *(const u64*)(xb + (size_t)1 * HW);
    u64 x2 = *(const u64*)(xb + (size_t)2 * HW);
    u64 x3 = *(const u64*)(xb + (size_t)3 * HW);

    #pragma unroll 1
    for (int c = 0; c < 256; c += 4) {
        int cn = (c < 252) ? c + 4 : c;
        u64 n0 = *(const u64*)(xb + (size_t)(cn + 0) * HW);
        u64 n1 = *(const u64*)(xb + (size_t)(cn + 1) * HW);
        u64 n2 = *(const u64*)(xb + (size_t)(cn + 2) * HW);
        u64 n3 = *(const u64*)(xb + (size_t)(cn + 3) * HW);
        #pragma unroll
        for (int k = 0; k < K_DIM; k++) {
            ulonglong2 wA = *(const ulonglong2*)&wd[k * 256 + c];
            ulonglong2 wB = *(const ulonglong2*)&wd[k * 256 + c + 2];
            a[k] = ffma2(wA.x, x0, a[k]);
            a[k] = ffma2(wA.y, x1, a[k]);
            a[k] = ffma2(wB.x, x2, a[k]);
            a[k] = ffma2(wB.y, x3, a[k]);
        }
        x0 = n0; x1 = n1; x2 = n2; x3 = n3;
    }

    float* gp = g_pre + (size_t)split * NHALF + ((size_t)b * K_DIM) * HW + p0;
    #pragma unroll
    for (int k = 0; k < K_DIM; k++)
        *(u64*)(gp + (size_t)k * HW) = a[k];
}

// ============================================================
// K3b: out = half0 + half1. float4 vectorized. grid 2432 x 256.
// ============================================================
__global__ void __launch_bounds__(256) k_comb(float* __restrict__ out)
{
    int i = blockIdx.x * 256 + threadIdx.x;
    float4 u = ((const float4*)g_pre)[i];
    float4 v = ((const float4*)(g_pre + NHALF))[i];
    ((float4*)out)[i] = make_float4(u.x + v.x, u.y + v.y, u.z + v.z, u.w + v.w);
}

// ============================================================
extern "C" void kernel_launch(void* const* d_in, const int* in_sizes, int n_in,
                              void* d_out, int out_size)
{
    const float* x  = (const float*)d_in[0];
    const float* Wm = (const float*)d_in[1];
    const float* bm = (const float*)d_in[2];
    const float* Wf = (const float*)d_in[3];
    const float* bf = (const float*)d_in[4];
    float* out = (float*)d_out;

    const int nv4 = NHALF / 4 / 256;         // 2432 blocks

    k_mask   <<<dim3(32, 2, B_DIM), 256>>>(x, Wm, bm);
    k_pool   <<<dim3(2, S_CHUNKS, B_DIM), 256>>>(x);
    k_cf     <<<dim3(K_DIM, B_DIM), 512>>>();
    k_filters<<<dim3(K_DIM, 8, B_DIM), 128>>>(Wf, bf);
    k_pred   <<<dim3(32, 2, B_DIM), 256>>>(x);
    k_comb   <<<nv4, 256>>>(out);
}

// round 15
// speedup vs baseline: 1.2684x; 1.2684x over previous
#include <cuda_runtime.h>

#define C_DIM 512
#define K_DIM 19
#define K_PAD 20                       // padded class dim (pool partial layout)
#define KH    10                       // classes per pool-ksplit CTA
#define HW    16384
#define B_DIM 8
#define S_CHUNKS 16                    // pool chunks (1024 positions each)
#define NHALF (B_DIM * K_DIM * HW)     // elements per csplit partial half

typedef unsigned long long u64;

// ---- f32x2 packed helpers ----
__device__ __forceinline__ u64 pk2(float lo, float hi) {
    u64 r; asm("mov.b64 %0, {%1, %2};" : "=l"(r) : "f"(lo), "f"(hi)); return r;
}
__device__ __forceinline__ void upk2(u64 v, float& lo, float& hi) {
    asm("mov.b64 {%0, %1}, %2;" : "=f"(lo), "=f"(hi) : "l"(v));
}
__device__ __forceinline__ u64 ffma2(u64 a, u64 b, u64 c) {
    u64 d; asm("fma.rn.f32x2 %0, %1, %2, %3;" : "=l"(d) : "l"(a), "l"(b), "l"(c)); return d;
}

// Static scratch
__device__ float g_pre[2 * NHALF];                             // csplit partials (19.9MB)
__device__ float g_partial[B_DIM * S_CHUNKS * K_PAD * C_DIM];  // pooling partials (5.2MB)
__device__ float g_filters[B_DIM * K_DIM * C_DIM];             // dynamic filters

// ============================================================
// K1: pre-mask partial over half the channels -> g_pre.
// grid (32 pos-tiles, 2 csplit, 8 b), 128 thr, 4 pos/thread.
// Dup'd-pair weights in smem (broadcast LDS.128 = 2 ch, 4 FFMA2/wf).
// Manual x double-buffer -> MLP 4.  (R11-measured configuration.)
// ============================================================
__global__ void __launch_bounds__(128, 4) k_mask(
    const float* __restrict__ x, const float* __restrict__ Wm,
    const float* __restrict__ bm)
{
    __shared__ __align__(16) u64 wd[K_DIM * 256];   // 38912 B
    int tid = threadIdx.x;
    int split = blockIdx.y, b = blockIdx.z;
    int c0 = split * 256;

    for (int i = tid; i < K_DIM * 256; i += 128) {
        float w = Wm[(i >> 8) * C_DIM + c0 + (i & 255)];
        wd[i] = pk2(w, w);
    }
    __syncthreads();

    int p0 = blockIdx.x * 512 + tid * 4;
    const float* xb = x + ((size_t)b * C_DIM + c0) * HW + p0;

    u64 a0[K_DIM], a1[K_DIM];
    #pragma unroll
    for (int k = 0; k < K_DIM; k++) {
        float bv = (split == 0) ? __ldg(&bm[k]) : 0.0f;
        a0[k] = pk2(bv, bv); a1[k] = a0[k];
    }

    ulonglong2 xa = *(const ulonglong2*)(xb + (size_t)0 * HW);
    ulonglong2 xc = *(const ulonglong2*)(xb + (size_t)1 * HW);

    #pragma unroll 1
    for (int c = 0; c < 256; c += 2) {
        int cn = (c < 254) ? c + 2 : 254;          // clamped prefetch
        ulonglong2 xa_n = *(const ulonglong2*)(xb + (size_t)(cn + 0) * HW);
        ulonglong2 xc_n = *(const ulonglong2*)(xb + (size_t)(cn + 1) * HW);
        #pragma unroll
        for (int k = 0; k < K_DIM; k++) {
            ulonglong2 w = *(const ulonglong2*)&wd[k * 256 + c];
            a0[k] = ffma2(w.x, xa.x, a0[k]);
            a1[k] = ffma2(w.x, xa.y, a1[k]);
            a0[k] = ffma2(w.y, xc.x, a0[k]);
            a1[k] = ffma2(w.y, xc.y, a1[k]);
        }
        xa = xa_n; xc = xc_n;
    }

    float* gp = g_pre + (size_t)split * NHALF + ((size_t)b * K_DIM) * HW + p0;
    #pragma unroll
    for (int k = 0; k < K_DIM; k++) {
        ulonglong2 v; v.x = a0[k]; v.y = a1[k];
        *(ulonglong2*)(gp + (size_t)k * HW) = v;
    }
}

// ============================================================
// K2: pooling partials. grid (2 ksplit, 16 chunks, 8 b), 256 thr.
// Each CTA: 10 classes (padded), ALL 512 channels, chunk=1024 pos.
// mask = sigmoid(h0+h1) computed INLINE while staging into smem.
// Lane owns a channel-QUAD: one mask LDS.64 feeds 4 FFMA2.
// (R11-measured configuration.)
// ============================================================
__global__ void __launch_bounds__(256, 2) k_pool(const float* __restrict__ x)
{
    __shared__ u64 m2[KH * 512];   // 40960 B
    int tid = threadIdx.x;
    int ksplit = blockIdx.x, chunk = blockIdx.y, b = blockIdx.z;
    int p0 = chunk * 1024;
    int K0 = ksplit * KH;

    for (int i = tid; i < KH * 512; i += 256) {
        int kh = i >> 9, j = i & 511;
        int k = K0 + kh;
        if (k < K_DIM) {
            size_t off = ((size_t)b * K_DIM + k) * HW + p0 + 2 * j;
            u64 h0 = *(const u64*)(g_pre + off);
            u64 h1 = *(const u64*)(g_pre + NHALF + off);
            float a0, a1, b0, b1;
            upk2(h0, a0, a1); upk2(h1, b0, b1);
            float s0 = 1.0f / (1.0f + __expf(-(a0 + b0)));
            float s1 = 1.0f / (1.0f + __expf(-(a1 + b1)));
            m2[i] = pk2(s0, s1);
        } else {
            m2[i] = 0ull;
        }
    }
    __syncthreads();

    int warp = tid >> 5, lane = tid & 31;
    const float inv = 1.0f / (float)HW;
    const float* xbase = x + (size_t)b * C_DIM * HW + p0;

    for (int i = 0; i < 16; i++) {          // 8 warps x 16 = 128 quads = 512 ch
        int cbase = 4 * (warp + 8 * i);
        const float* xp0 = xbase + (size_t)(cbase + 0) * HW;
        const float* xp1 = xbase + (size_t)(cbase + 1) * HW;
        const float* xp2 = xbase + (size_t)(cbase + 2) * HW;
        const float* xp3 = xbase + (size_t)(cbase + 3) * HW;

        u64 a[4 * KH];
        #pragma unroll
        for (int j = 0; j < 4 * KH; j++) a[j] = 0ull;

        #pragma unroll 2
        for (int t = 0; t < 16; t++) {      // 16 pair-steps x 32 lanes = 512 pairs
            int idx = lane + 32 * t;
            u64 xv0 = *(const u64*)(xp0 + 2 * idx);
            u64 xv1 = *(const u64*)(xp1 + 2 * idx);
            u64 xv2 = *(const u64*)(xp2 + 2 * idx);
            u64 xv3 = *(const u64*)(xp3 + 2 * idx);
            #pragma unroll
            for (int kh = 0; kh < KH; kh++) {
                u64 m = m2[kh * 512 + idx];
                a[kh * 4 + 0] = ffma2(m, xv0, a[kh * 4 + 0]);
                a[kh * 4 + 1] = ffma2(m, xv1, a[kh * 4 + 1]);
                a[kh * 4 + 2] = ffma2(m, xv2, a[kh * 4 + 2]);
                a[kh * 4 + 3] = ffma2(m, xv3, a[kh * 4 + 3]);
            }
        }

        #pragma unroll
        for (int kh = 0; kh < KH; kh++) {
            float s[4];
            #pragma unroll
            for (int j = 0; j < 4; j++) {
                float lo, hi; upk2(a[kh * 4 + j], lo, hi); s[j] = lo + hi;
            }
            #pragma unroll
            for (int off = 16; off > 0; off >>= 1) {
                #pragma unroll
                for (int j = 0; j < 4; j++)
                    s[j] += __shfl_xor_sync(0xffffffffu, s[j], off);
            }
            if (lane == 0) {
                float* gp = &g_partial[(((size_t)b * S_CHUNKS + chunk) * K_PAD + K0 + kh) * C_DIM + cbase];
                gp[0] = s[0] * inv; gp[1] = s[1] * inv;
                gp[2] = s[2] * inv; gp[3] = s[3] * inv;
            }
        }
    }
}

// ============================================================
// K2c: filters GEMV with FUSED class_feat reduction.
// grid (19, 8 osplit, 8 b) = 1216 CTAs, block 128.
// Prologue: reduce 16 chunk-partials for (b,k) into smem cf[512]
// (L2-hot, 32KB/CTA). Then 16 o per warp, 4 concurrent rows.
// ============================================================
__global__ void __launch_bounds__(128) k_filters(
    const float* __restrict__ Wf, const float* __restrict__ bf)
{
    __shared__ float cf[C_DIM];
    int k = blockIdx.x, osplit = blockIdx.y, b = blockIdx.z;
    int tid = threadIdx.x;
    int warp = tid >> 5, lane = tid & 31;

    // fused k_cf: cf[c] = sum over chunks of g_partial
    for (int c = tid; c < C_DIM; c += 128) {
        const float* gp = g_partial + ((size_t)b * S_CHUNKS * K_PAD + k) * C_DIM + c;
        float sum = 0.0f;
        #pragma unroll 8
        for (int s = 0; s < S_CHUNKS; s++)
            sum += gp[(size_t)s * K_PAD * C_DIM];
        cf[c] = sum;
    }
    __syncthreads();

    const float4* cf4 = (const float4*)cf;
    float4 cfr[4];
    #pragma unroll
    for (int j = 0; j < 4; j++) cfr[j] = cf4[lane + 32 * j];

    int obase = osplit * 64 + warp * 16;
    for (int g = 0; g < 4; g++) {
        int o = obase + 4 * g;
        const float4* w0 = (const float4*)(Wf + ((size_t)k * C_DIM + o + 0) * C_DIM);
        const float4* w1 = (const float4*)(Wf + ((size_t)k * C_DIM + o + 1) * C_DIM);
        const float4* w2 = (const float4*)(Wf + ((size_t)k * C_DIM + o + 2) * C_DIM);
        const float4* w3 = (const float4*)(Wf + ((size_t)k * C_DIM + o + 3) * C_DIM);

        float acc0 = 0.f, acc1 = 0.f, acc2 = 0.f, acc3 = 0.f;
        #pragma unroll
        for (int j = 0; j < 4; j++) {
            int idx = lane + 32 * j;
            float4 a = w0[idx], bb = w1[idx], cc = w2[idx], dd = w3[idx];
            float4 f = cfr[j];
            acc0 += a.x * f.x + a.y * f.y + a.z * f.z + a.w * f.w;
            acc1 += bb.x * f.x + bb.y * f.y + bb.z * f.z + bb.w * f.w;
            acc2 += cc.x * f.x + cc.y * f.y + cc.z * f.z + cc.w * f.w;
            acc3 += dd.x * f.x + dd.y * f.y + dd.z * f.z + dd.w * f.w;
        }
        #pragma unroll
        for (int off = 16; off > 0; off >>= 1) {
            acc0 += __shfl_xor_sync(0xffffffffu, acc0, off);
            acc1 += __shfl_xor_sync(0xffffffffu, acc1, off);
            acc2 += __shfl_xor_sync(0xffffffffu, acc2, off);
            acc3 += __shfl_xor_sync(0xffffffffu, acc3, off);
        }
        if (lane < 4) {
            float v = (lane == 0) ? acc0 : (lane == 1) ? acc1 : (lane == 2) ? acc2 : acc3;
            g_filters[((size_t)b * K_DIM + k) * C_DIM + o + lane] =
                v + bf[k * C_DIM + o + lane];
        }
    }
}

// ============================================================
// K3: pred partial over half the channels (same shape as k_mask).
// Launch position #4 -> gets the ncu capture next round.
// ============================================================
__global__ void __launch_bounds__(128, 4) k_pred(const float* __restrict__ x)
{
    __shared__ __align__(16) u64 wd[K_DIM * 256];
    int tid = threadIdx.x;
    int split = blockIdx.y, b = blockIdx.z;
    int c0 = split * 256;

    const float* fb = g_filters + (size_t)b * K_DIM * C_DIM;
    for (int i = tid; i < K_DIM * 256; i += 128) {
        float w = fb[(i >> 8) * C_DIM + c0 + (i & 255)];
        wd[i] = pk2(w, w);
    }
    __syncthreads();

    int p0 = blockIdx.x * 512 + tid * 4;
    const float* xb = x + ((size_t)b * C_DIM + c0) * HW + p0;

    u64 a0[K_DIM], a1[K_DIM];
    #pragma unroll
    for (int k = 0; k < K_DIM; k++) { a0[k] = 0ull; a1[k] = 0ull; }

    ulonglong2 xa = *(const ulonglong2*)(xb + (size_t)0 * HW);
    ulonglong2 xc = *(const ulonglong2*)(xb + (size_t)1 * HW);

    #pragma unroll 1
    for (int c = 0; c < 256; c += 2) {
        int cn = (c < 254) ? c + 2 : 254;
        ulonglong2 xa_n = *(const ulonglong2*)(xb + (size_t)(cn + 0) * HW);
        ulonglong2 xc_n = *(const ulonglong2*)(xb + (size_t)(cn + 1) * HW);
        #pragma unroll
        for (int k = 0; k < K_DIM; k++) {
            ulonglong2 w = *(const ulonglong2*)&wd[k * 256 + c];
            a0[k] = ffma2(w.x, xa.x, a0[k]);
            a1[k] = ffma2(w.x, xa.y, a1[k]);
            a0[k] = ffma2(w.y, xc.x, a0[k]);
            a1[k] = ffma2(w.y, xc.y, a1[k]);
        }
        xa = xa_n; xc = xc_n;
    }

    float* gp = g_pre + (size_t)split * NHALF + ((size_t)b * K_DIM) * HW + p0;
    #pragma unroll
    for (int k = 0; k < K_DIM; k++) {
        ulonglong2 v; v.x = a0[k]; v.y = a1[k];
        *(ulonglong2*)(gp + (size_t)k * HW) = v;
    }
}

// ============================================================
// K3b: out = half0 + half1. float4 vectorized. grid 2432 x 256.
// ============================================================
__global__ void __launch_bounds__(256) k_comb(float* __restrict__ out)
{
    int i = blockIdx.x * 256 + threadIdx.x;
    float4 u = ((const float4*)g_pre)[i];
    float4 v = ((const float4*)(g_pre + NHALF))[i];
    ((float4*)out)[i] = make_float4(u.x + v.x, u.y + v.y, u.z + v.z, u.w + v.w);
}

// ============================================================
extern "C" void kernel_launch(void* const* d_in, const int* in_sizes, int n_in,
                              void* d_out, int out_size)
{
    const float* x  = (const float*)d_in[0];
    const float* Wm = (const float*)d_in[1];
    const float* bm = (const float*)d_in[2];
    const float* Wf = (const float*)d_in[3];
    const float* bf = (const float*)d_in[4];
    float* out = (float*)d_out;

    const int nv4 = NHALF / 4 / 256;         // 2432 blocks

    k_mask   <<<dim3(32, 2, B_DIM), 128>>>(x, Wm, bm);
    k_pool   <<<dim3(2, S_CHUNKS, B_DIM), 256>>>(x);
    k_filters<<<dim3(K_DIM, 8, B_DIM), 128>>>(Wf, bf);
    k_pred   <<<dim3(32, 2, B_DIM), 128>>>(x);   // launch #4: ncu target
    k_comb   <<<nv4, 256>>>(out);
}